// round 17
// baseline (speedup 1.0000x reference)
#include <cuda_runtime.h>
#include <cuda_bf16.h>
#include <math.h>
#include <stdint.h>

#define NNODE 50000
#define NEDGE 800000
#define ETOT  (NEDGE + NNODE)
#define FDIM  128
#define HEADS 8
#define CH    16
#define NF    ((size_t)NNODE * FDIM)

#define CSR_B 512
#define CSR_G 98

// ---------------- static scratch --------------------------------------------
__device__ float g_XL[NNODE * FDIM];
__device__ float g_XR[NNODE * FDIM];
__device__ float g_ACC[NNODE * FDIM];
__device__ float g_H[NNODE * FDIM];
__device__ __nv_bfloat16 g_whi[4 * 16384];
__device__ __nv_bfloat16 g_wlo[4 * 16384];
__device__ float g_bnA[FDIM];
__device__ float g_bnB[FDIM];
__device__ int g_counts[NNODE];
__device__ int g_rowptr[NNODE + 1];
__device__ int g_wptr[NNODE];
__device__ int g_esrc[ETOT];
__device__ int g_bsum[CSR_G];
__device__ int g_sync0, g_sync1, g_sync2;

__device__ __forceinline__ uint32_t smem_u32(const void* p) {
    uint32_t a;
    asm("{ .reg .u64 t; cvta.to.shared.u64 t, %1; cvt.u32.u64 %0, t; }" : "=r"(a) : "l"(p));
    return a;
}

// ---------------- setup ------------------------------------------------------
__global__ void setup_kernel(const float* __restrict__ Wl1, const float* __restrict__ Wr1,
                             const float* __restrict__ Wl2, const float* __restrict__ Wr2,
                             const float* __restrict__ bias1,
                             const float* __restrict__ bw, const float* __restrict__ bb,
                             const float* __restrict__ rm, const float* __restrict__ rv) {
    int i = blockIdx.x * 256 + threadIdx.x;
    if (i < 4 * 16384) {
        int m = i >> 14, k = i & 16383;
        const float* src = (m == 0) ? Wl1 : (m == 1) ? Wr1 : (m == 2) ? Wl2 : Wr2;
        float v = src[k];
        __nv_bfloat16 h = __float2bfloat16_rn(v);
        g_whi[i] = h;
        g_wlo[i] = __float2bfloat16_rn(v - __bfloat162float(h));
    }
    if (i < NNODE) g_counts[i] = 0;
    if (i < FDIM) {
        float A = bw[i] * rsqrtf(rv[i] + 1e-5f);
        g_bnA[i] = A;
        g_bnB[i] = (bias1[i] - rm[i]) * A + bb[i];
    }
    if (i == 0) { g_sync0 = 0; g_sync1 = 0; g_sync2 = 0; }
}

// ---------------- one-kernel CSR build ---------------------------------------
__device__ __forceinline__ void grid_barrier(int* cnt) {
    __syncthreads();
    if (threadIdx.x == 0) {
        __threadfence();
        atomicAdd(cnt, 1);
        while (atomicAdd(cnt, 0) < CSR_G) { }
    }
    __syncthreads();
}

__global__ void __launch_bounds__(CSR_B, 1)
csr_mega_kernel(const int* __restrict__ ei) {
    const int t = threadIdx.x, b = blockIdx.x;
    const int nth = CSR_B * CSR_G;
    const int tidg = b * CSR_B + t;
    const int lane = t & 31, wid = t >> 5;
    __shared__ int swarp[16];
    __shared__ int s_bcast;

    for (int e = tidg; e < ETOT; e += nth) {
        int d = (e < NEDGE) ? ei[NEDGE + e] : (e - NEDGE);
        atomicAdd(&g_counts[d], 1);
    }
    grid_barrier(&g_sync0);

    int v = (tidg < NNODE) ? g_counts[tidg] : 0;
    int incl = v;
#pragma unroll
    for (int d = 1; d < 32; d <<= 1) {
        int n = __shfl_up_sync(0xffffffffu, incl, d);
        if (lane >= d) incl += n;
    }
    if (lane == 31) swarp[wid] = incl;
    __syncthreads();
    if (wid == 0) {
        int s = (lane < 16) ? swarp[lane] : 0;
        int si = s;
#pragma unroll
        for (int d = 1; d < 16; d <<= 1) {
            int n = __shfl_up_sync(0xffffffffu, si, d);
            if (lane >= d) si += n;
        }
        if (lane < 16) swarp[lane] = si - s;
        if (lane == 15) g_bsum[b] = si;
    }
    __syncthreads();
    int excl_in_block = swarp[wid] + incl - v;

    grid_barrier(&g_sync1);

    {
        int pv = (t < b) ? __ldcg(&g_bsum[t]) : 0;
#pragma unroll
        for (int d = 16; d > 0; d >>= 1) pv += __shfl_down_sync(0xffffffffu, pv, d);
        __syncthreads();
        if (lane == 0) swarp[wid] = pv;
        __syncthreads();
        if (t == 0) {
            int s = 0;
#pragma unroll
            for (int w = 0; w < 16; w++) s += swarp[w];
            s_bcast = s;
        }
        __syncthreads();
    }
    int excl = s_bcast + excl_in_block;
    if (tidg < NNODE) { g_rowptr[tidg] = excl; g_wptr[tidg] = excl; }
    if (tidg == NNODE - 1) g_rowptr[NNODE] = ETOT;

    grid_barrier(&g_sync2);

    for (int e = tidg; e < ETOT; e += nth) {
        int s, d;
        if (e < NEDGE) { s = ei[e]; d = ei[NEDGE + e]; }
        else { s = d = e - NEDGE; }
        int pos = atomicAdd(&g_wptr[d], 1);
        g_esrc[pos] = s;
    }
}

// ---------------- dual GEMM via mma.sync bf16 hi/lo 3-pass -------------------
#define PAD_ROW 272
#define SM_A_HI 0
#define SM_A_LO (128 * PAD_ROW)
#define SM_B_HI (2 * 128 * PAD_ROW)
#define SM_B_LO (SM_B_HI + 256 * PAD_ROW)
#define SM_TOT  (SM_B_LO + 256 * PAD_ROW)

#define LDM4(r, addr) \
    asm volatile("ldmatrix.sync.aligned.m8n8.x4.shared.b16 {%0,%1,%2,%3}, [%4];" \
        : "=r"((r)[0]), "=r"((r)[1]), "=r"((r)[2]), "=r"((r)[3]) : "r"(addr))

#define MMA16816(c, a, b0, b1) \
    asm volatile("mma.sync.aligned.m16n8k16.row.col.f32.bf16.bf16.f32 " \
        "{%0,%1,%2,%3}, {%4,%5,%6,%7}, {%8,%9}, {%0,%1,%2,%3};" \
        : "+f"((c)[0]), "+f"((c)[1]), "+f"((c)[2]), "+f"((c)[3]) \
        : "r"((a)[0]), "r"((a)[1]), "r"((a)[2]), "r"((a)[3]), "r"(b0), "r"(b1))

// split 2 fp32 into packed bf16x2 hi + lo (1 packed cvt each way)
__device__ __forceinline__ void split2(float vx, float vy, uint32_t& hi, uint32_t& lo) {
    asm("cvt.rn.bf16x2.f32 %0, %1, %2;" : "=r"(hi) : "f"(vy), "f"(vx));
    float hx = __uint_as_float(hi << 16);
    float hy = __uint_as_float(hi & 0xFFFF0000u);
    asm("cvt.rn.bf16x2.f32 %0, %1, %2;" : "=r"(lo) : "f"(vy - hy), "f"(vx - hx));
}

#define CPA16(dst, src) \
    asm volatile("cp.async.cg.shared.global [%0], [%1], 16;" :: "r"(dst), "l"(src))

__global__ void __launch_bounds__(512, 1)
gemm_mma_kernel(const float* __restrict__ A,
                const __nv_bfloat16* __restrict__ Bhi,
                const __nv_bfloat16* __restrict__ Blo,
                const float* __restrict__ bl, const float* __restrict__ br,
                float* __restrict__ Yl, float* __restrict__ Yr, int M) {
    extern __shared__ char sm[];
    uint32_t sbase = smem_u32(sm);
    int tid = threadIdx.x;
    int row0 = blockIdx.x * 128;

    // B copy via cp.async (no register round-trip)
#pragma unroll
    for (int i = 0; i < 8; i++) {
        int idx = tid + i * 512;
        int r = idx >> 4;
        int kc = idx & 15;
        uint32_t off = (uint32_t)r * PAD_ROW + (uint32_t)kc * 16;
        CPA16(sbase + SM_B_HI + off, Bhi + (size_t)r * 128 + kc * 8);
        CPA16(sbase + SM_B_LO + off, Blo + (size_t)r * 128 + kc * 8);
    }
    asm volatile("cp.async.commit_group;" ::: "memory");

    // A load + hi/lo split (packed cvts)
#pragma unroll
    for (int i = 0; i < 4; i++) {
        int idx = tid + i * 512;
        int r = idx >> 4;
        int kc = idx & 15;
        int grow = row0 + r;
        float4 v0 = make_float4(0.f, 0.f, 0.f, 0.f), v1 = v0;
        if (grow < M) {
            const float4* src = (const float4*)(A + (size_t)grow * 128 + kc * 8);
            v0 = src[0]; v1 = src[1];
        }
        uint4 hi, lo;
        split2(v0.x, v0.y, hi.x, lo.x);
        split2(v0.z, v0.w, hi.y, lo.y);
        split2(v1.x, v1.y, hi.z, lo.z);
        split2(v1.z, v1.w, hi.w, lo.w);
        uint32_t off = (uint32_t)r * PAD_ROW + (uint32_t)kc * 16;
        *(uint4*)(sm + SM_A_HI + off) = hi;
        *(uint4*)(sm + SM_A_LO + off) = lo;
    }
    asm volatile("cp.async.wait_group 0;" ::: "memory");
    __syncthreads();

    int lane = tid & 31, wid = tid >> 5;
    int warp_m = wid & 3, warp_n = wid >> 2;

    uint32_t aoff0 = (uint32_t)(warp_m * 32 + (lane & 15)) * PAD_ROW + ((lane >> 4) * 16);
    uint32_t aoff1 = aoff0 + 16 * PAD_ROW;
    uint32_t aHi0 = sbase + SM_A_HI + aoff0, aHi1 = sbase + SM_A_HI + aoff1;
    uint32_t aLo0 = sbase + SM_A_LO + aoff0, aLo1 = sbase + SM_A_LO + aoff1;
    uint32_t boff = (uint32_t)(warp_n * 64 + (lane & 7) + ((lane >> 4) & 1) * 8) * PAD_ROW
                  + (((lane >> 3) & 1) * 16);
    uint32_t bHiB = sbase + SM_B_HI + boff;
    uint32_t bLoB = sbase + SM_B_LO + boff;

    float c[2][8][4];
#pragma unroll
    for (int t = 0; t < 2; t++)
#pragma unroll
        for (int n = 0; n < 8; n++)
#pragma unroll
            for (int q = 0; q < 4; q++) c[t][n][q] = 0.f;

#pragma unroll
    for (int p = 0; p < 3; p++) {
        uint32_t ab0 = (p < 2) ? aHi0 : aLo0;
        uint32_t ab1 = (p < 2) ? aHi1 : aLo1;
        uint32_t bb  = (p == 1) ? bLoB : bHiB;
#pragma unroll
        for (int ks = 0; ks < 8; ks++) {
            uint32_t kb = ks * 32;
            uint32_t a0[4], a1[4];
            LDM4(a0, ab0 + kb);
            LDM4(a1, ab1 + kb);
#pragma unroll
            for (int g = 0; g < 4; g++) {
                uint32_t b[4];
                LDM4(b, bb + g * (16 * PAD_ROW) + kb);
                MMA16816(c[0][2 * g],     a0, b[0], b[1]);
                MMA16816(c[0][2 * g + 1], a0, b[2], b[3]);
                MMA16816(c[1][2 * g],     a1, b[0], b[1]);
                MMA16816(c[1][2 * g + 1], a1, b[2], b[3]);
            }
        }
    }

    const float* bias = (warp_n < 2) ? bl : br;
    float* Y = (warp_n < 2) ? Yl : Yr;
    int ncol0 = (warp_n & 1) * 64;
#pragma unroll
    for (int t = 0; t < 2; t++) {
        int r = row0 + warp_m * 32 + t * 16 + (lane >> 2);
#pragma unroll
        for (int nt = 0; nt < 8; nt++) {
            int col = ncol0 + nt * 8 + (lane & 3) * 2;
            float b0 = bias[col], b1 = bias[col + 1];
            if (r < M)
                *(float2*)(Y + (size_t)r * 128 + col) =
                    make_float2(c[t][nt][0] + b0, c[t][nt][1] + b1);
            if (r + 8 < M)
                *(float2*)(Y + (size_t)(r + 8) * 128 + col) =
                    make_float2(c[t][nt][2] + b0, c[t][nt][3] + b1);
        }
    }
}

// ---------------- fused GAT aggregation --------------------------------------
typedef unsigned long long u64t;
__device__ __forceinline__ u64t pk2(float lo, float hi) {
    u64t r;
    asm("mov.b64 %0, {%1, %2};" : "=l"(r) : "f"(lo), "f"(hi));
    return r;
}

// score partial for one edge: sum over this lane's 4 channels of att*leaky(x+r)
__device__ __forceinline__ float edge_partial(float4 x, u64t r01, u64t r23, float4 a) {
    u64t x01 = pk2(x.x, x.y), x23 = pk2(x.z, x.w), t01, t23;
    asm("add.rn.f32x2 %0, %1, %2;" : "=l"(t01) : "l"(x01), "l"(r01));
    asm("add.rn.f32x2 %0, %1, %2;" : "=l"(t23) : "l"(x23), "l"(r23));
    float t0, t1, t2, t3;
    asm("mov.b64 {%0, %1}, %2;" : "=f"(t0), "=f"(t1) : "l"(t01));
    asm("mov.b64 {%0, %1}, %2;" : "=f"(t2), "=f"(t3) : "l"(t23));
    t0 = fmaxf(t0, 0.2f * t0); t1 = fmaxf(t1, 0.2f * t1);
    t2 = fmaxf(t2, 0.2f * t2); t3 = fmaxf(t3, 0.2f * t3);
    return t0 * a.x + t1 * a.y + t2 * a.z + t3 * a.w;
}

__device__ __forceinline__ void acc_edge(u64t& a01, u64t& a23, float ev, float4 x) {
    u64t ee, x01 = pk2(x.x, x.y), x23 = pk2(x.z, x.w);
    asm("mov.b64 %0, {%1, %1};" : "=l"(ee) : "f"(ev));
    asm("fma.rn.f32x2 %0, %1, %2, %0;" : "+l"(a01) : "l"(ee), "l"(x01));
    asm("fma.rn.f32x2 %0, %1, %2, %0;" : "+l"(a23) : "l"(ee), "l"(x23));
}

__global__ void gat_agg_kernel(const float* __restrict__ xl,
                               const float* __restrict__ xr,
                               const float* __restrict__ att,
                               float* __restrict__ out, int fuse_bn) {
    int w = (blockIdx.x * blockDim.x + threadIdx.x) >> 5;
    if (w >= NNODE) return;
    int l = threadIdx.x & 31;

    const float4* xl4 = (const float4*)xl;
    float4 r = ((const float4*)xr)[(size_t)w * 32 + l];
    float4 a = ((const float4*)att)[l];
    u64t r01 = pk2(r.x, r.y), r23 = pk2(r.z, r.w);
    u64t acc01 = pk2(0.f, 0.f), acc23 = pk2(0.f, 0.f);
    float den = 0.f;

    int beg = g_rowptr[w], end = g_rowptr[w + 1];
    for (int base = beg; base < end; base += 32) {
        int n = end - base; if (n > 32) n = 32;
        int sid = (base + l < end) ? g_esrc[base + l] : 0;
        int j = 0;
        for (; j + 4 <= n; j += 4) {
            int s0 = __shfl_sync(0xffffffffu, sid, j);
            int s1 = __shfl_sync(0xffffffffu, sid, j + 1);
            int s2 = __shfl_sync(0xffffffffu, sid, j + 2);
            int s3 = __shfl_sync(0xffffffffu, sid, j + 3);
            float4 x0 = xl4[(size_t)s0 * 32 + l];
            float4 x1 = xl4[(size_t)s1 * 32 + l];
            float4 x2 = xl4[(size_t)s2 * 32 + l];
            float4 x3 = xl4[(size_t)s3 * 32 + l];
            float p0 = edge_partial(x0, r01, r23, a);
            float p1 = edge_partial(x1, r01, r23, a);
            float p2 = edge_partial(x2, r01, r23, a);
            float p3 = edge_partial(x3, r01, r23, a);
            p0 += __shfl_xor_sync(0xffffffffu, p0, 1);
            p1 += __shfl_xor_sync(0xffffffffu, p1, 1);
            p2 += __shfl_xor_sync(0xffffffffu, p2, 1);
            p3 += __shfl_xor_sync(0xffffffffu, p3, 1);
            p0 += __shfl_xor_sync(0xffffffffu, p0, 2);
            p1 += __shfl_xor_sync(0xffffffffu, p1, 2);
            p2 += __shfl_xor_sync(0xffffffffu, p2, 2);
            p3 += __shfl_xor_sync(0xffffffffu, p3, 2);
            float e0 = __expf(p0), e1 = __expf(p1);
            float e2 = __expf(p2), e3 = __expf(p3);
            den += (e0 + e1) + (e2 + e3);
            acc_edge(acc01, acc23, e0, x0);
            acc_edge(acc01, acc23, e1, x1);
            acc_edge(acc01, acc23, e2, x2);
            acc_edge(acc01, acc23, e3, x3);
        }
        for (; j < n; j++) {
            int s0 = __shfl_sync(0xffffffffu, sid, j);
            float4 x0 = xl4[(size_t)s0 * 32 + l];
            float p0 = edge_partial(x0, r01, r23, a);
            p0 += __shfl_xor_sync(0xffffffffu, p0, 1);
            p0 += __shfl_xor_sync(0xffffffffu, p0, 2);
            float e0 = __expf(p0);
            den += e0;
            acc_edge(acc01, acc23, e0, x0);
        }
    }
    float a0, a1v, a2, a3;
    asm("mov.b64 {%0, %1}, %2;" : "=f"(a0), "=f"(a1v) : "l"(acc01));
    asm("mov.b64 {%0, %1}, %2;" : "=f"(a2), "=f"(a3) : "l"(acc23));
    float inv = 1.f / den;
    float4 v = make_float4(a0 * inv, a1v * inv, a2 * inv, a3 * inv);
    if (fuse_bn) {
        float4 A = ((const float4*)g_bnA)[l];
        float4 B = ((const float4*)g_bnB)[l];
        v.x = v.x * A.x + B.x; v.x = v.x > 0.f ? v.x : expm1f(v.x);
        v.y = v.y * A.y + B.y; v.y = v.y > 0.f ? v.y : expm1f(v.y);
        v.z = v.z * A.z + B.z; v.z = v.z > 0.f ? v.z : expm1f(v.z);
        v.w = v.w * A.w + B.w; v.w = v.w > 0.f ? v.w : expm1f(v.w);
    }
    ((float4*)out)[(size_t)w * 32 + l] = v;
}

// ---------------- final: mean heads + bias2 + skip GEMM + LayerNorm ----------
__global__ void final_kernel(const float* __restrict__ out2,
                             const float* __restrict__ bias2,
                             const float* __restrict__ x,
                             const float* __restrict__ Wskip,
                             const float* __restrict__ lnw, const float* __restrict__ lnb,
                             float* __restrict__ yout) {
    __shared__ float sWs[128 * 16];
    __shared__ float sX[16 * 132];
    int t = threadIdx.x;
    for (int i = t; i < 16 * 128; i += 256) {
        int j = i >> 7, k = i & 127;
        sWs[k * 16 + j] = Wskip[i];
    }
    int n0 = blockIdx.x * 16;
    for (int i = t; i < 16 * 128; i += 256) {
        int r = i >> 7, k = i & 127;
        sX[r * 132 + k] = x[(size_t)(n0 + r) * 128 + k];
    }
    __syncthreads();

    int warp = t >> 5, lane = t & 31;
    int nl = warp * 2 + (lane >> 4);
    int n = n0 + nl;
    int j = lane & 15;

    const float* o2 = out2 + (size_t)n * FDIM;
    float m = 0.f;
#pragma unroll
    for (int h = 0; h < HEADS; h++) m += o2[h * CH + j];
    m *= 0.125f;

    const float* xs = sX + nl * 132;
    float skip = 0.f;
#pragma unroll 8
    for (int k = 0; k < 128; k++) skip += xs[k] * sWs[k * 16 + j];

    float y = m + bias2[j] + skip;

    float sum = y;
#pragma unroll
    for (int dd = 1; dd < 16; dd <<= 1) sum += __shfl_xor_sync(0xffffffffu, sum, dd);
    float mu = sum * (1.f / 16.f);
    float diff = y - mu;
    float vs = diff * diff;
#pragma unroll
    for (int dd = 1; dd < 16; dd <<= 1) vs += __shfl_xor_sync(0xffffffffu, vs, dd);
    float var = vs * (1.f / 16.f);
    yout[(size_t)n * 16 + j] = diff * rsqrtf(var + 1e-5f) * lnw[j] + lnb[j];
}

// ---------------- launch -----------------------------------------------------
extern "C" void kernel_launch(void* const* d_in, const int* in_sizes, int n_in,
                              void* d_out, int out_size) {
    const float* x      = (const float*)d_in[0];
    const int*   ei     = (const int*)d_in[1];
    const float* Wl1    = (const float*)d_in[2];
    const float* bl1    = (const float*)d_in[3];
    const float* Wr1    = (const float*)d_in[4];
    const float* br1    = (const float*)d_in[5];
    const float* att1   = (const float*)d_in[6];
    const float* bias1  = (const float*)d_in[7];
    const float* bn_w   = (const float*)d_in[8];
    const float* bn_b   = (const float*)d_in[9];
    const float* bn_rm  = (const float*)d_in[10];
    const float* bn_rv  = (const float*)d_in[11];
    const float* Wl2    = (const float*)d_in[12];
    const float* bl2    = (const float*)d_in[13];
    const float* Wr2    = (const float*)d_in[14];
    const float* br2    = (const float*)d_in[15];
    const float* att2   = (const float*)d_in[16];
    const float* bias2  = (const float*)d_in[17];
    const float* Wskip  = (const float*)d_in[18];
    const float* ln_w   = (const float*)d_in[19];
    const float* ln_b   = (const float*)d_in[20];
    float* yout = (float*)d_out;

    float *XL, *XR, *ACC, *H;
    __nv_bfloat16 *whi, *wlo;
    cudaGetSymbolAddress((void**)&XL, g_XL);
    cudaGetSymbolAddress((void**)&XR, g_XR);
    cudaGetSymbolAddress((void**)&ACC, g_ACC);
    cudaGetSymbolAddress((void**)&H, g_H);
    cudaGetSymbolAddress((void**)&whi, g_whi);
    cudaGetSymbolAddress((void**)&wlo, g_wlo);

    cudaFuncSetAttribute(gemm_mma_kernel, cudaFuncAttributeMaxDynamicSharedMemorySize, SM_TOT);
    const int gemm_grid = (NNODE + 127) / 128;

    setup_kernel<<<(4 * 16384 + 255) / 256, 256>>>(Wl1, Wr1, Wl2, Wr2,
                                                   bias1, bn_w, bn_b, bn_rm, bn_rv);
    csr_mega_kernel<<<CSR_G, CSR_B>>>(ei);

    gemm_mma_kernel<<<gemm_grid, 512, SM_TOT>>>(x, whi, wlo, bl1, br1, XL, XR, NNODE);
    gat_agg_kernel<<<(NNODE * 32 + 255) / 256, 256>>>(XL, XR, att1, H, 1);

    gemm_mma_kernel<<<gemm_grid, 512, SM_TOT>>>(H, whi + 32768, wlo + 32768, bl2, br2, XL, XR, NNODE);
    gat_agg_kernel<<<(NNODE * 32 + 255) / 256, 256>>>(XL, XR, att2, ACC, 0);

    final_kernel<<<NNODE / 16, 256>>>(ACC, bias2, x, Wskip, ln_w, ln_b, yout);
}